// round 1
// baseline (speedup 1.0000x reference)
#include <cuda_runtime.h>
#include <math.h>

#define N       1024
#define NN      (N * N)
#define RESTART 16
#define NV      (RESTART + 1)
#define K2C     0.3f
#define EPSF    1e-12f
#define NBLK    512
#define TPB     256
#define NCYCLES 4

// ---------------- device scratch (static: no allocations allowed) ----------
__device__ float g_V[NV][NN];       // Krylov basis
__device__ float g_w[NN];           // work vector
__device__ float g_x[NN];           // current solution
__device__ float g_part[NV][NBLK];  // block partial sums
__device__ float g_h[NV];
__device__ float g_h2[NV];
__device__ float g_Hm[NV * RESTART];
__device__ float g_y[RESTART];
__device__ float g_beta;
__device__ float g_inv;

// ---------------- helpers ---------------------------------------------------
__device__ __forceinline__ float stencilA(const float* __restrict__ u, int i) {
    // A(u) = -lap(u) + k2*u = (4 + k2)*u - (up + down + left + right), periodic
    int ix   = i & (N - 1);
    int iy   = i >> 10;
    int base = iy << 10;
    float c = u[i];
    float s = u[base + ((ix - 1) & (N - 1))]
            + u[base + ((ix + 1) & (N - 1))]
            + u[((((iy - 1) & (N - 1))) << 10) + ix]
            + u[((((iy + 1) & (N - 1))) << 10) + ix];
    return (4.0f + K2C) * c - s;
}

__device__ __forceinline__ float warpSum(float v) {
#pragma unroll
    for (int o = 16; o > 0; o >>= 1) v += __shfl_down_sync(0xffffffffu, v, o);
    return v;
}

// reduce NV per-thread accumulators to g_part[k][blockIdx.x]
__device__ __forceinline__ void blockReducePart(float* acc) {
    __shared__ float sred[NV][TPB / 32];
    int lane = threadIdx.x & 31, warp = threadIdx.x >> 5;
#pragma unroll
    for (int k = 0; k < NV; k++) {
        float v = warpSum(acc[k]);
        if (lane == 0) sred[k][warp] = v;
    }
    __syncthreads();
    if (threadIdx.x < NV) {
        float s = 0.f;
#pragma unroll
        for (int w = 0; w < TPB / 32; w++) s += sred[threadIdx.x][w];
        g_part[threadIdx.x][blockIdx.x] = s;
    }
}

__device__ __forceinline__ void blockReduce1(float v) {
    __shared__ float sred1[TPB / 32];
    int lane = threadIdx.x & 31, warp = threadIdx.x >> 5;
    v = warpSum(v);
    if (lane == 0) sred1[warp] = v;
    __syncthreads();
    if (threadIdx.x == 0) {
        float s = 0.f;
#pragma unroll
        for (int w = 0; w < TPB / 32; w++) s += sred1[w];
        g_part[0][blockIdx.x] = s;
    }
}

// ---------------- kernels ----------------------------------------------------
__global__ void k_init_x(const float* __restrict__ guess) {
    for (int i = blockIdx.x * blockDim.x + threadIdx.x; i < NN; i += gridDim.x * blockDim.x)
        g_x[i] = guess[i];
}

__global__ void k_out(float* __restrict__ out) {
    for (int i = blockIdx.x * blockDim.x + threadIdx.x; i < NN; i += gridDim.x * blockDim.x)
        out[i] = g_x[i];
}

// r = b - A(x), partial sum of r^2
__global__ void k_residual(const float* __restrict__ b) {
    float acc = 0.f;
    for (int i = blockIdx.x * blockDim.x + threadIdx.x; i < NN; i += gridDim.x * blockDim.x) {
        float r = b[i] - stencilA(g_x, i);
        g_w[i]  = r;
        acc += r * r;
    }
    blockReduce1(acc);
}

// w = A(V[j]); partial dots h_k = <V[k], w> for k<=j
__global__ void k_arnA(int j) {
    float acc[NV];
#pragma unroll
    for (int k = 0; k < NV; k++) acc[k] = 0.f;
    const float* __restrict__ u = g_V[j];
    for (int i = blockIdx.x * blockDim.x + threadIdx.x; i < NN; i += gridDim.x * blockDim.x) {
        float w = stencilA(u, i);
        g_w[i]  = w;
#pragma unroll
        for (int k = 0; k < NV; k++)
            if (k <= j) acc[k] += g_V[k][i] * w;
    }
    blockReducePart(acc);
}

// pass 1: w -= sum h[k] V[k]; partial dots h2_k = <V[k], w_new>
// pass 2: w -= sum h2[k] V[k]; partial sum of w_new^2
__global__ void k_update(int j, int pass) {
    __shared__ float hs[NV];
    if (threadIdx.x < NV)
        hs[threadIdx.x] = (pass == 1) ? g_h[threadIdx.x] : g_h2[threadIdx.x];
    __syncthreads();

    float acc[NV];
#pragma unroll
    for (int k = 0; k < NV; k++) acc[k] = 0.f;

    for (int i = blockIdx.x * blockDim.x + threadIdx.x; i < NN; i += gridDim.x * blockDim.x) {
        float vk[NV];
#pragma unroll
        for (int k = 0; k < NV; k++) vk[k] = (k <= j) ? g_V[k][i] : 0.f;
        float w = g_w[i];
#pragma unroll
        for (int k = 0; k < NV; k++)
            if (k <= j) w -= hs[k] * vk[k];
        g_w[i] = w;
        if (pass == 1) {
#pragma unroll
            for (int k = 0; k < NV; k++) acc[k] += vk[k] * w;
        } else {
            acc[0] += w * w;
        }
    }
    if (pass == 1) blockReducePart(acc);
    else           blockReduce1(acc[0]);
}

// mode 0: beta = sqrt(sum part[0]); g_inv = 1/(beta+eps); zero Hm
// mode 1: g_h[k]  = sum part[k]   (k<=j else 0)
// mode 2: g_h2[k] = sum part[k]; Hm[k][j] = g_h[k] + g_h2[k]
// mode 3: hn = sqrt(sum part[0]); Hm[j+1][j] = hn; g_inv = 1/(hn+eps)
__global__ void k_reduce(int j, int mode) {
    __shared__ float s[TPB];
    int t = threadIdx.x;
    if (mode == 0 || mode == 3) {
        float v = g_part[0][t] + g_part[0][t + TPB];
        s[t] = v;
        __syncthreads();
#pragma unroll
        for (int off = TPB / 2; off > 0; off >>= 1) {
            if (t < off) s[t] += s[t + off];
            __syncthreads();
        }
        if (t == 0) {
            float nr = sqrtf(s[0]);
            if (mode == 0) {
                g_beta = nr;
                g_inv  = 1.0f / (nr + EPSF);
            } else {
                g_Hm[(j + 1) * RESTART + j] = nr;
                g_inv = 1.0f / (nr + EPSF);
            }
        }
        if (mode == 0) {
            __syncthreads();
            for (int idx = t; idx < NV * RESTART; idx += TPB) g_Hm[idx] = 0.f;
        }
    } else {
        for (int k = 0; k < NV; k++) {
            float v = (k <= j) ? (g_part[k][t] + g_part[k][t + TPB]) : 0.f;
            s[t] = v;
            __syncthreads();
#pragma unroll
            for (int off = TPB / 2; off > 0; off >>= 1) {
                if (t < off) s[t] += s[t + off];
                __syncthreads();
            }
            if (t == 0) {
                if (mode == 1) g_h[k] = s[0];
                else {
                    g_h2[k] = s[0];
                    g_Hm[k * RESTART + j] = g_h[k] + s[0];
                }
            }
            __syncthreads();
        }
    }
}

// V[vidx] = w * g_inv
__global__ void k_scale(int vidx) {
    float inv = g_inv;
    float* __restrict__ dst = g_V[vidx];
    for (int i = blockIdx.x * blockDim.x + threadIdx.x; i < NN; i += gridDim.x * blockDim.x)
        dst[i] = g_w[i] * inv;
}

// solve (Hm^T Hm + eps I) y = Hm^T e1 * beta  (tiny 16x16, single thread)
__global__ void k_solve() {
    if (threadIdx.x != 0 || blockIdx.x != 0) return;
    float G[RESTART][RESTART];
    float rhs[RESTART];
    for (int a = 0; a < RESTART; a++) {
        for (int b = 0; b < RESTART; b++) {
            float su = 0.f;
            for (int r = 0; r < NV; r++)
                su += g_Hm[r * RESTART + a] * g_Hm[r * RESTART + b];
            G[a][b] = su + ((a == b) ? EPSF : 0.f);
        }
        rhs[a] = g_Hm[0 * RESTART + a] * g_beta;
    }
    // Gaussian elimination (G is SPD)
    for (int p = 0; p < RESTART; p++) {
        float piv = G[p][p];
        for (int r = p + 1; r < RESTART; r++) {
            float f = G[r][p] / piv;
            for (int c = p; c < RESTART; c++) G[r][c] -= f * G[p][c];
            rhs[r] -= f * rhs[p];
        }
    }
    for (int p = RESTART - 1; p >= 0; p--) {
        float su = rhs[p];
        for (int c = p + 1; c < RESTART; c++) su -= G[p][c] * rhs[c];
        rhs[p] = su / G[p][p];
    }
    for (int k = 0; k < RESTART; k++) g_y[k] = rhs[k];
}

// x += sum_k y[k] * V[k]   (k = 0..15)
__global__ void k_xupdate() {
    __shared__ float ys[RESTART];
    if (threadIdx.x < RESTART) ys[threadIdx.x] = g_y[threadIdx.x];
    __syncthreads();
    for (int i = blockIdx.x * blockDim.x + threadIdx.x; i < NN; i += gridDim.x * blockDim.x) {
        float s = g_x[i];
#pragma unroll
        for (int k = 0; k < RESTART; k++) s += ys[k] * g_V[k][i];
        g_x[i] = s;
    }
}

// ---------------- host orchestration ----------------------------------------
extern "C" void kernel_launch(void* const* d_in, const int* in_sizes, int n_in,
                              void* d_out, int out_size) {
    (void)in_sizes; (void)n_in; (void)out_size;
    const float* src   = (const float*)d_in[0];
    const float* guess = (const float*)d_in[1];
    float* out = (float*)d_out;

    k_init_x<<<NBLK, TPB>>>(guess);

    for (int c = 0; c < NCYCLES; c++) {
        k_residual<<<NBLK, TPB>>>(src);
        k_reduce<<<1, TPB>>>(0, 0);
        k_scale<<<NBLK, TPB>>>(0);

        for (int j = 0; j < RESTART; j++) {
            k_arnA<<<NBLK, TPB>>>(j);
            k_reduce<<<1, TPB>>>(j, 1);
            k_update<<<NBLK, TPB>>>(j, 1);
            k_reduce<<<1, TPB>>>(j, 2);
            k_update<<<NBLK, TPB>>>(j, 2);
            k_reduce<<<1, TPB>>>(j, 3);
            k_scale<<<NBLK, TPB>>>(j + 1);
        }

        k_solve<<<1, 1>>>();
        k_xupdate<<<NBLK, TPB>>>();
    }

    k_out<<<NBLK, TPB>>>(out);
}

// round 2
// speedup vs baseline: 1.6591x; 1.6591x over previous
#include <cuda_runtime.h>
#include <math.h>

#define N       1024
#define NN      (N * N)
#define NN4     (NN / 4)
#define RESTART 16
#define NV      (RESTART + 1)
#define K2C     0.3f
#define ACOEF   (4.0f + K2C)
#define EPSF    1e-12f
#define TPB     256
#define GRID    (NN4 / TPB)   /* 1024 blocks, one float4 per thread */
#define NCYCLES 4

// ---------------- device scratch (static: allocations are forbidden) --------
__device__ float4 g_V[NV][NN4];     // Krylov basis (V[16] never materialized)
__device__ float4 g_wA[NN4];        // work vector, double-buffered
__device__ float4 g_wB[NN4];
__device__ float4 g_x[NN4];         // current solution
__device__ float  g_part[NV][GRID]; // per-block partial sums
__device__ float  g_h[NV];
__device__ float  g_h2[NV];
__device__ float  g_Hm[NV * RESTART];  // zero-init; rows k>j+1 of col j stay 0 forever
__device__ float  g_y[RESTART];
__device__ float  g_beta;
__device__ float  g_inv;
__device__ unsigned g_cnt;          // last-block-done counter (reset by last block)

// ---------------- helpers ----------------------------------------------------
__device__ __forceinline__ float dot4(float4 a, float4 b) {
    return a.x * b.x + a.y * b.y + a.z * b.z + a.w * b.w;
}

// 5-point periodic Helmholtz stencil on a float4 (row = idx>>8, 256 float4/row)
__device__ __forceinline__ float4 stencil4(const float4* __restrict__ u4, int idx) {
    int row = idx >> 8;
    int c4  = idx & 255;
    float4 C = u4[idx];
    float4 U = u4[(((row - 1) & (N - 1)) << 8) | c4];
    float4 D = u4[(((row + 1) & (N - 1)) << 8) | c4];
    const float* uf = (const float*)u4;
    int rb = row << 10;
    float L = uf[rb | (((c4 << 2) - 1) & (N - 1))];
    float R = uf[rb | (((c4 << 2) + 4) & (N - 1))];
    float4 z;
    z.x = ACOEF * C.x - (L   + C.y + U.x + D.x);
    z.y = ACOEF * C.y - (C.x + C.z + U.y + D.y);
    z.z = ACOEF * C.z - (C.y + C.w + U.z + D.z);
    z.w = ACOEF * C.w - (C.z + R   + U.w + D.w);
    return z;
}

__device__ __forceinline__ float warpSum(float v) {
#pragma unroll
    for (int o = 16; o > 0; o >>= 1) v += __shfl_down_sync(0xffffffffu, v, o);
    return v;
}

// write per-block partial sums for NK accumulators, then fence
template <int NK>
__device__ __forceinline__ void blockPartials(const float* acc) {
    __shared__ float sred[NK][TPB / 32];
    int lane = threadIdx.x & 31, warp = threadIdx.x >> 5;
#pragma unroll
    for (int k = 0; k < NK; k++) {
        float v = warpSum(acc[k]);
        if (lane == 0) sred[k][warp] = v;
    }
    __syncthreads();
    if (threadIdx.x < NK) {
        float s = 0.f;
#pragma unroll
        for (int w = 0; w < TPB / 32; w++) s += sred[threadIdx.x][w];
        g_part[threadIdx.x][blockIdx.x] = s;
        __threadfence();
    }
    __syncthreads();
}

// true in exactly the block that finishes last
__device__ __forceinline__ bool isLastBlock() {
    __shared__ unsigned s_last;
    if (threadIdx.x == 0)
        s_last = (atomicAdd(&g_cnt, 1u) == (unsigned)(gridDim.x - 1));
    __syncthreads();
    return s_last != 0;
}

// last block: reduce g_part rows 0..nk-1 into shared s_tot[]
__device__ __forceinline__ void finalTotals(float* s_tot, int nk) {
    int t = threadIdx.x, lane = t & 31, warp = t >> 5;
    __shared__ float sred2[TPB / 32];
    for (int k = 0; k < nk; k++) {
        float s = 0.f;
#pragma unroll
        for (int b = 0; b < GRID / TPB; b++) s += g_part[k][t + b * TPB];
        s = warpSum(s);
        if (lane == 0) sred2[warp] = s;
        __syncthreads();
        if (t == 0) {
            float q = 0.f;
#pragma unroll
            for (int w = 0; w < TPB / 32; w++) q += sred2[w];
            s_tot[k] = q;
        }
        __syncthreads();
    }
}

// ---------------- kernels ------------------------------------------------------
__global__ void k_init(const float4* __restrict__ guess) {
    int i = blockIdx.x * TPB + threadIdx.x;
    g_x[i] = guess[i];
}

// w(A-buffer) = b - A(x); last block: beta, inv = 1/(beta+eps)
__global__ void k_resid(const float4* __restrict__ b) {
    int i = blockIdx.x * TPB + threadIdx.x;
    float4 z = stencil4(g_x, i);
    float4 bb = b[i];
    float4 r;
    r.x = bb.x - z.x; r.y = bb.y - z.y; r.z = bb.z - z.z; r.w = bb.w - z.w;
    g_wA[i] = r;
    float acc[1];
    acc[0] = dot4(r, r);
    blockPartials<1>(acc);
    if (isLastBlock()) {
        __shared__ float s_tot[1];
        finalTotals(s_tot, 1);
        if (threadIdx.x == 0) {
            float be = sqrtf(s_tot[0]);
            g_beta = be;
            g_inv  = 1.0f / (be + EPSF);
            g_cnt  = 0;
        }
    }
}

// fused scale + stencil + first CGS dots:
//  V[j] = w_in*inv ; z = A(w_in) ; w_out = z*inv ;
//  h_k = inv*<V[k],z> (k<j), h_j = inv^2*<w_in,z>
__global__ void k_f1(int j) {
    const float4* __restrict__ win = (j & 1) ? g_wB : g_wA;
    float4* __restrict__       wout = (j & 1) ? g_wA : g_wB;
    float inv = g_inv;
    int i = blockIdx.x * TPB + threadIdx.x;

    float4 z = stencil4(win, i);
    float4 C = win[i];
    float4 vj;
    vj.x = C.x * inv; vj.y = C.y * inv; vj.z = C.z * inv; vj.w = C.w * inv;
    g_V[j][i] = vj;
    float4 wn;
    wn.x = z.x * inv; wn.y = z.y * inv; wn.z = z.z * inv; wn.w = z.w * inv;
    wout[i] = wn;

    float acc[NV];
#pragma unroll
    for (int k = 0; k < NV; k++) acc[k] = 0.f;
#pragma unroll
    for (int k = 0; k < NV; k++) {
        if (k < j)       acc[k] = dot4(g_V[k][i], z);
        else if (k == j) acc[k] = dot4(C, z);
    }
    blockPartials<NV>(acc);
    if (isLastBlock()) {
        __shared__ float s_tot[NV];
        finalTotals(s_tot, j + 1);
        float iv = g_inv;
        int t = threadIdx.x;
        if (t <= j) g_h[t] = s_tot[t] * ((t == j) ? iv * iv : iv);
        if (t == 0) g_cnt = 0;
    }
}

// pass 1 projection: w -= sum h[k] V[k]; dots h2_k = <V[k], w_new>
__global__ void k_f2(int j) {
    float4* __restrict__ w4 = (j & 1) ? g_wA : g_wB;
    __shared__ float hs[NV];
    if (threadIdx.x < NV) hs[threadIdx.x] = g_h[threadIdx.x];
    __syncthreads();

    int i = blockIdx.x * TPB + threadIdx.x;
    float4 w = w4[i];
    float4 vk[NV];
#pragma unroll
    for (int k = 0; k < NV; k++) {
        if (k <= j) {
            float4 v = g_V[k][i];
            vk[k] = v;
            float h = hs[k];
            w.x -= h * v.x; w.y -= h * v.y; w.z -= h * v.z; w.w -= h * v.w;
        }
    }
    w4[i] = w;
    float acc[NV];
#pragma unroll
    for (int k = 0; k < NV; k++) acc[k] = (k <= j) ? dot4(vk[k], w) : 0.f;

    blockPartials<NV>(acc);
    if (isLastBlock()) {
        __shared__ float s_tot[NV];
        finalTotals(s_tot, j + 1);
        int t = threadIdx.x;
        if (t <= j) {
            float h2 = s_tot[t];
            g_h2[t] = h2;
            g_Hm[t * RESTART + j] = g_h[t] + h2;
        }
        if (t == 0) g_cnt = 0;
    }
}

// pass 2 projection: w -= sum h2[k] V[k]; norm; last block: Hm[j+1][j]=hn, inv
__global__ void k_f3(int j) {
    float4* __restrict__ w4 = (j & 1) ? g_wA : g_wB;
    __shared__ float hs[NV];
    if (threadIdx.x < NV) hs[threadIdx.x] = g_h2[threadIdx.x];
    __syncthreads();

    int i = blockIdx.x * TPB + threadIdx.x;
    float4 w = w4[i];
#pragma unroll
    for (int k = 0; k < NV; k++) {
        if (k <= j) {
            float4 v = g_V[k][i];
            float h = hs[k];
            w.x -= h * v.x; w.y -= h * v.y; w.z -= h * v.z; w.w -= h * v.w;
        }
    }
    w4[i] = w;
    float acc[1];
    acc[0] = dot4(w, w);
    blockPartials<1>(acc);
    if (isLastBlock()) {
        __shared__ float s_tot[1];
        finalTotals(s_tot, 1);
        if (threadIdx.x == 0) {
            float hn = sqrtf(s_tot[0]);
            g_Hm[(j + 1) * RESTART + j] = hn;
            g_inv = 1.0f / (hn + EPSF);
            g_cnt = 0;
        }
    }
}

// tiny solve: (Hm^T Hm + eps I) y = beta * Hm^T e1
__global__ void k_solve() {
    if (threadIdx.x != 0) return;
    float G[RESTART][RESTART];
    float rhs[RESTART];
    for (int a = 0; a < RESTART; a++) {
        for (int b = 0; b < RESTART; b++) {
            float su = 0.f;
            for (int r = 0; r < NV; r++)
                su += g_Hm[r * RESTART + a] * g_Hm[r * RESTART + b];
            G[a][b] = su + ((a == b) ? EPSF : 0.f);
        }
        rhs[a] = g_Hm[a] * g_beta;   // row 0 of Hm
    }
    for (int p = 0; p < RESTART; p++) {
        float piv = G[p][p];
        for (int r = p + 1; r < RESTART; r++) {
            float f = G[r][p] / piv;
            for (int c = p; c < RESTART; c++) G[r][c] -= f * G[p][c];
            rhs[r] -= f * rhs[p];
        }
    }
    for (int p = RESTART - 1; p >= 0; p--) {
        float su = rhs[p];
        for (int c = p + 1; c < RESTART; c++) su -= G[p][c] * rhs[c];
        rhs[p] = su / G[p][p];
    }
    for (int k = 0; k < RESTART; k++) g_y[k] = rhs[k];
}

// x += sum_k y[k] V[k]; optionally also emit to out (final cycle)
__global__ void k_xupd(float4* __restrict__ out) {
    __shared__ float ys[RESTART];
    if (threadIdx.x < RESTART) ys[threadIdx.x] = g_y[threadIdx.x];
    __syncthreads();
    int i = blockIdx.x * TPB + threadIdx.x;
    float4 s = g_x[i];
#pragma unroll
    for (int k = 0; k < RESTART; k++) {
        float4 v = g_V[k][i];
        float y = ys[k];
        s.x += y * v.x; s.y += y * v.y; s.z += y * v.z; s.w += y * v.w;
    }
    g_x[i] = s;
    if (out) out[i] = s;
}

// ---------------- host orchestration ----------------------------------------
extern "C" void kernel_launch(void* const* d_in, const int* in_sizes, int n_in,
                              void* d_out, int out_size) {
    (void)in_sizes; (void)n_in; (void)out_size;
    const float4* src   = (const float4*)d_in[0];
    const float4* guess = (const float4*)d_in[1];
    float4* out = (float4*)d_out;

    k_init<<<GRID, TPB>>>(guess);

    for (int c = 0; c < NCYCLES; c++) {
        k_resid<<<GRID, TPB>>>(src);
        for (int j = 0; j < RESTART; j++) {
            k_f1<<<GRID, TPB>>>(j);
            k_f2<<<GRID, TPB>>>(j);
            k_f3<<<GRID, TPB>>>(j);
        }
        k_solve<<<1, 32>>>();
        k_xupd<<<GRID, TPB>>>(c == NCYCLES - 1 ? out : nullptr);
    }
}

// round 3
// speedup vs baseline: 2.6264x; 1.5830x over previous
#include <cuda_runtime.h>
#include <math.h>

#define N       1024
#define NN      (N * N)
#define NN4     (NN / 4)
#define RESTART 16
#define NV      17
#define K2C     0.3f
#define ACOEF   (4.0f + K2C)
#define EPSF    1e-12f
#define TPB     256
#define NBLK    512
#define HALF    (NN4 / 2)        /* 131072: each thread does i and i+HALF */
#define NCYC    4
#define NPART   17               /* rows 0..15 = dots, row 16 = norm */

// ---------------- device scratch (allocations forbidden) --------------------
__device__ float4 g_V[RESTART][NN4];   // V[16] never materialized
__device__ float4 g_wA[NN4];           // KA input / KB output
__device__ float4 g_wB[NN4];           // KA output (z) / KB input
__device__ float4 g_x[NN4];
__device__ float  g_part[NPART][NBLK];
__device__ float  g_h[RESTART];
__device__ float  g_h2[RESTART];
__device__ float  g_Hm[NV * RESTART];  // static zeros below subdiag persist
__device__ float  g_y[RESTART];
__device__ float  g_beta, g_inv;
__device__ unsigned g_cnt;

// ---------------- helpers ----------------------------------------------------
struct Off { int c, u, d, l, r; };

__device__ __forceinline__ Off mkoff(int idx) {
    Off o;
    int row = idx >> 8, c4 = idx & 255;
    o.c = idx;
    o.u = (((row - 1) & (N - 1)) << 8) | c4;
    o.d = (((row + 1) & (N - 1)) << 8) | c4;
    int rb = row << 10;
    o.l = rb | (((c4 << 2) - 1) & (N - 1));
    o.r = rb | (((c4 << 2) + 4) & (N - 1));
    return o;
}

// load center f4 + neighbor-sum f4 (periodic 5-point footprint)
__device__ __forceinline__ void loadCN(const float4* __restrict__ u4, const Off& o,
                                       float4& C, float4& NS) {
    C = u4[o.c];
    float4 U = u4[o.u], D = u4[o.d];
    const float* uf = (const float*)u4;
    float L = uf[o.l], R = uf[o.r];
    NS.x = L   + C.y + U.x + D.x;
    NS.y = C.x + C.z + U.y + D.y;
    NS.z = C.y + C.w + U.z + D.z;
    NS.w = C.z + R   + U.w + D.w;
}

__device__ __forceinline__ float dot4(float4 a, float4 b) {
    return a.x * b.x + a.y * b.y + a.z * b.z + a.w * b.w;
}

__device__ __forceinline__ float warpSum(float v) {
#pragma unroll
    for (int o = 16; o > 0; o >>= 1) v += __shfl_down_sync(0xffffffffu, v, o);
    return v;
}

// per-block partials for rows k<nk (+row16 if withNorm), then fence
__device__ __forceinline__ void blockPartials(const float* acc, int nk, bool withNorm) {
    __shared__ float sred[NPART][TPB / 32];
    int lane = threadIdx.x & 31, warp = threadIdx.x >> 5;
#pragma unroll
    for (int k = 0; k < RESTART; k++)
        if (k < nk) {
            float v = warpSum(acc[k]);
            if (lane == 0) sred[k][warp] = v;
        }
    if (withNorm) {
        float v = warpSum(acc[16]);
        if (lane == 0) sred[16][warp] = v;
    }
    __syncthreads();
    int t = threadIdx.x;
    if (t < nk || (withNorm && t == 16)) {
        float s = 0.f;
#pragma unroll
        for (int w = 0; w < TPB / 32; w++) s += sred[t][w];
        g_part[t][blockIdx.x] = s;
        __threadfence();
    }
    __syncthreads();
}

__device__ __forceinline__ bool isLastBlock() {
    __shared__ unsigned s_last;
    if (threadIdx.x == 0)
        s_last = (atomicAdd(&g_cnt, 1u) == (unsigned)(gridDim.x - 1));
    __syncthreads();
    return s_last != 0;
}

// last block: totals for rows k<nk (+16). one row per warp, strided.
__device__ __forceinline__ void finalTotals(float* s_tot, int nk, bool withNorm) {
    int warp = threadIdx.x >> 5, lane = threadIdx.x & 31;
    for (int k = warp; k < NPART; k += TPB / 32) {
        bool active = (k < nk) || (withNorm && k == 16);
        if (!active) continue;
        float s = 0.f;
        for (int b = lane; b < NBLK; b += 32) s += g_part[k][b];
        s = warpSum(s);
        if (lane == 0) s_tot[k] = s;
    }
    __syncthreads();
}

// ---------------- kernels ------------------------------------------------------
__global__ void __launch_bounds__(TPB) k_init(const float4* __restrict__ guess) {
    int i1 = blockIdx.x * TPB + threadIdx.x;
    g_x[i1] = guess[i1];
    g_x[i1 + HALF] = guess[i1 + HALF];
}

// r = b - A(x); beta, inv
__global__ void __launch_bounds__(TPB) k_resid(const float4* __restrict__ b) {
    int i1 = blockIdx.x * TPB + threadIdx.x, i2 = i1 + HALF;
    Off o1 = mkoff(i1), o2 = mkoff(i2);
    float4 c, n, bb, r1, r2;

    loadCN(g_x, o1, c, n);
    bb = b[i1];
    r1.x = bb.x - (ACOEF * c.x - n.x);
    r1.y = bb.y - (ACOEF * c.y - n.y);
    r1.z = bb.z - (ACOEF * c.z - n.z);
    r1.w = bb.w - (ACOEF * c.w - n.w);
    g_wA[i1] = r1;

    loadCN(g_x, o2, c, n);
    bb = b[i2];
    r2.x = bb.x - (ACOEF * c.x - n.x);
    r2.y = bb.y - (ACOEF * c.y - n.y);
    r2.z = bb.z - (ACOEF * c.z - n.z);
    r2.w = bb.w - (ACOEF * c.w - n.w);
    g_wA[i2] = r2;

    float acc[NPART];
    acc[16] = dot4(r1, r1) + dot4(r2, r2);
    blockPartials(acc, 0, true);
    if (isLastBlock()) {
        __shared__ float tot[NPART];
        finalTotals(tot, 0, true);
        if (threadIdx.x == 0) {
            float be = sqrtf(tot[16]);
            g_beta = be;
            g_inv  = 1.0f / (be + EPSF);
            g_cnt  = 0;
        }
    }
}

// KA(j): wc = wA - sum_{k<j} h2_k V[k] (deferred CGS2 pass-2 of step j-1);
//        V[j] = wc*inv; z = inv*A(wc) (stencil linearity, 5-pt reads);
//        wB = z; h_k = <V[k], z> (k<j), h_j = inv*<wc, z>
__global__ void __launch_bounds__(TPB, 4) k_KA(int j) {
    __shared__ float h2s[RESTART];
    if (threadIdx.x < RESTART) h2s[threadIdx.x] = g_h2[threadIdx.x];
    __syncthreads();

    int i1 = blockIdx.x * TPB + threadIdx.x, i2 = i1 + HALF;
    Off o1 = mkoff(i1), o2 = mkoff(i2);
    float4 c1, n1, c2, n2;
    loadCN(g_wA, o1, c1, n1);
    loadCN(g_wA, o2, c2, n2);

#pragma unroll
    for (int k = 0; k < RESTART; k++)
        if (k < j) {
            float hk = h2s[k];
            float4 vc, vn;
            loadCN(g_V[k], o1, vc, vn);
            c1.x -= hk * vc.x; c1.y -= hk * vc.y; c1.z -= hk * vc.z; c1.w -= hk * vc.w;
            n1.x -= hk * vn.x; n1.y -= hk * vn.y; n1.z -= hk * vn.z; n1.w -= hk * vn.w;
            loadCN(g_V[k], o2, vc, vn);
            c2.x -= hk * vc.x; c2.y -= hk * vc.y; c2.z -= hk * vc.z; c2.w -= hk * vc.w;
            n2.x -= hk * vn.x; n2.y -= hk * vn.y; n2.z -= hk * vn.z; n2.w -= hk * vn.w;
        }

    float inv = g_inv;
    float4 vj;
    vj.x = c1.x * inv; vj.y = c1.y * inv; vj.z = c1.z * inv; vj.w = c1.w * inv;
    g_V[j][i1] = vj;
    vj.x = c2.x * inv; vj.y = c2.y * inv; vj.z = c2.z * inv; vj.w = c2.w * inv;
    g_V[j][i2] = vj;

    float4 z1, z2;
    z1.x = inv * (ACOEF * c1.x - n1.x);
    z1.y = inv * (ACOEF * c1.y - n1.y);
    z1.z = inv * (ACOEF * c1.z - n1.z);
    z1.w = inv * (ACOEF * c1.w - n1.w);
    z2.x = inv * (ACOEF * c2.x - n2.x);
    z2.y = inv * (ACOEF * c2.y - n2.y);
    z2.z = inv * (ACOEF * c2.z - n2.z);
    z2.w = inv * (ACOEF * c2.w - n2.w);
    g_wB[i1] = z1;
    g_wB[i2] = z2;

    float accj = dot4(c1, z1) + dot4(c2, z2);   // scaled by inv at reduction

    float acc[NPART];
#pragma unroll
    for (int k = 0; k < NPART; k++) acc[k] = 0.f;
#pragma unroll
    for (int k = 0; k < RESTART; k++) {
        if (k < j)
            acc[k] = dot4(g_V[k][i1], z1) + dot4(g_V[k][i2], z2);
        else if (k == j)
            acc[k] = accj;
    }

    blockPartials(acc, j + 1, false);
    if (isLastBlock()) {
        __shared__ float tot[NPART];
        finalTotals(tot, j + 1, false);
        int t = threadIdx.x;
        if (t <= j) g_h[t] = tot[t] * ((t == j) ? g_inv : 1.0f);
        if (t == 0) g_cnt = 0;
    }
}

// KB(j): wA = wB - sum_{k<=j} h_k V[k]; h2_k = <V[k], wA>; norm;
//        Hm[k][j] = h+h2; hn = sqrt(max(norm - ||h2||^2, 0)); inv = 1/(hn+eps)
__global__ void __launch_bounds__(TPB, 4) k_KB(int j) {
    __shared__ float hs[RESTART];
    if (threadIdx.x < RESTART) hs[threadIdx.x] = g_h[threadIdx.x];
    __syncthreads();

    int i1 = blockIdx.x * TPB + threadIdx.x, i2 = i1 + HALF;
    float4 w1 = g_wB[i1], w2 = g_wB[i2];

#pragma unroll
    for (int k = 0; k < RESTART; k++)
        if (k <= j) {
            float hk = hs[k];
            float4 v = g_V[k][i1];
            w1.x -= hk * v.x; w1.y -= hk * v.y; w1.z -= hk * v.z; w1.w -= hk * v.w;
            v = g_V[k][i2];
            w2.x -= hk * v.x; w2.y -= hk * v.y; w2.z -= hk * v.z; w2.w -= hk * v.w;
        }
    g_wA[i1] = w1;
    g_wA[i2] = w2;

    float acc[NPART];
#pragma unroll
    for (int k = 0; k < NPART; k++) acc[k] = 0.f;
#pragma unroll
    for (int k = 0; k < RESTART; k++)
        if (k <= j)
            acc[k] = dot4(g_V[k][i1], w1) + dot4(g_V[k][i2], w2);
    acc[16] = dot4(w1, w1) + dot4(w2, w2);

    blockPartials(acc, j + 1, true);
    if (isLastBlock()) {
        __shared__ float tot[NPART];
        finalTotals(tot, j + 1, true);
        int t = threadIdx.x;
        if (t <= j) {
            g_h2[t] = tot[t];
            g_Hm[t * RESTART + j] = g_h[t] + tot[t];
        }
        __syncthreads();
        if (t == 0) {
            float ss = 0.f;
            for (int k = 0; k <= j; k++) ss += tot[k] * tot[k];
            float hn2 = tot[16] - ss;
            float hn  = sqrtf(fmaxf(hn2, 0.f));
            g_Hm[(j + 1) * RESTART + j] = hn;
            g_inv = 1.0f / (hn + EPSF);
            g_cnt = 0;
        }
    }
}

// tiny solve: (Hm^T Hm + eps I) y = beta * Hm^T e1
__global__ void k_solve() {
    if (threadIdx.x != 0) return;
    float G[RESTART][RESTART], rhs[RESTART];
    for (int a = 0; a < RESTART; a++) {
        for (int b = 0; b < RESTART; b++) {
            float su = 0.f;
            for (int r = 0; r < NV; r++)
                su += g_Hm[r * RESTART + a] * g_Hm[r * RESTART + b];
            G[a][b] = su + ((a == b) ? EPSF : 0.f);
        }
        rhs[a] = g_Hm[a] * g_beta;
    }
    for (int p = 0; p < RESTART; p++) {
        float piv = G[p][p];
        for (int r = p + 1; r < RESTART; r++) {
            float f = G[r][p] / piv;
            for (int c = p; c < RESTART; c++) G[r][c] -= f * G[p][c];
            rhs[r] -= f * rhs[p];
        }
    }
    for (int p = RESTART - 1; p >= 0; p--) {
        float su = rhs[p];
        for (int c = p + 1; c < RESTART; c++) su -= G[p][c] * rhs[c];
        rhs[p] = su / G[p][p];
    }
    for (int k = 0; k < RESTART; k++) g_y[k] = rhs[k];
}

// x += sum_k y_k V[k]; optionally emit
__global__ void __launch_bounds__(TPB) k_xupd(float4* __restrict__ out) {
    __shared__ float ys[RESTART];
    if (threadIdx.x < RESTART) ys[threadIdx.x] = g_y[threadIdx.x];
    __syncthreads();
    int i1 = blockIdx.x * TPB + threadIdx.x, i2 = i1 + HALF;
    float4 s1 = g_x[i1], s2 = g_x[i2];
#pragma unroll
    for (int k = 0; k < RESTART; k++) {
        float y = ys[k];
        float4 v = g_V[k][i1];
        s1.x += y * v.x; s1.y += y * v.y; s1.z += y * v.z; s1.w += y * v.w;
        v = g_V[k][i2];
        s2.x += y * v.x; s2.y += y * v.y; s2.z += y * v.z; s2.w += y * v.w;
    }
    g_x[i1] = s1;
    g_x[i2] = s2;
    if (out) { out[i1] = s1; out[i2] = s2; }
}

// ---------------- host orchestration ----------------------------------------
extern "C" void kernel_launch(void* const* d_in, const int* in_sizes, int n_in,
                              void* d_out, int out_size) {
    (void)in_sizes; (void)n_in; (void)out_size;
    const float4* src   = (const float4*)d_in[0];
    const float4* guess = (const float4*)d_in[1];
    float4* out = (float4*)d_out;

    k_init<<<NBLK, TPB>>>(guess);

    for (int c = 0; c < NCYC; c++) {
        k_resid<<<NBLK, TPB>>>(src);
        for (int j = 0; j < RESTART; j++) {
            k_KA<<<NBLK, TPB>>>(j);
            k_KB<<<NBLK, TPB>>>(j);
        }
        k_solve<<<1, 32>>>();
        k_xupd<<<NBLK, TPB>>>(c == NCYC - 1 ? out : nullptr);
    }
}